// round 9
// baseline (speedup 1.0000x reference)
#include <cuda_runtime.h>
#include <cstdint>

#define BB    16
#define CC    256
#define INTER 128
#define NN    2048
#define MSPLIT 8            // two 128-n slices per block

// ---------------- scratch ----------------
__device__ uint32_t d_Wtp [128 * 384];                 // bf16 pairs along k: [k2][m], m = theta|phi|g
__device__ uint32_t d_Wt2p[64 * 256];                  // W_w^T bf16 pairs along d: [d2][c]
__device__ float    d_bias[384];
__device__ uint32_t d_theta[(size_t)BB * INTER * (NN / 2)];   // bf16 pairs along n: [b][k][n2]
__device__ float    d_Mpart[(size_t)BB * MSPLIT * INTER * INTER];
__device__ float    d_Qt   [(size_t)BB * INTER * CC];  // [b][k][c]
__device__ uint32_t d_zb   [(size_t)BB * CC * (NN / 2)];      // z as bf16 pairs along n
__device__ float    d_sums [512];

// ---------------- helpers ----------------
__device__ __forceinline__ uint32_t bf2(float lo, float hi) {
    uint32_t r; asm("cvt.rn.bf16x2.f32 %0,%1,%2;" : "=r"(r) : "f"(hi), "f"(lo));
    return r;
}
__device__ __forceinline__ void mma16(float* c, const uint32_t* a, const uint32_t* b) {
    asm volatile("mma.sync.aligned.m16n8k16.row.col.f32.bf16.bf16.f32 "
        "{%0,%1,%2,%3},{%4,%5,%6,%7},{%8,%9},{%0,%1,%2,%3};"
        : "+f"(c[0]), "+f"(c[1]), "+f"(c[2]), "+f"(c[3])
        : "r"(a[0]), "r"(a[1]), "r"(a[2]), "r"(a[3]), "r"(b[0]), "r"(b[1]));
}

// ---------------- bf16 mma over one 16-k slab (slabs are [8][136]) ----------------
__device__ __forceinline__ void mma_tile16(
    const uint32_t (*As)[136], const uint32_t (*Bs)[136],
    float (&acc)[4][4][4], int wm, int wn, int gid, int tig)
{
    uint32_t a[4][4], b[4][2];
    #pragma unroll
    for (int mt = 0; mt < 4; mt++) {
        int row = wm + mt * 16 + gid;
        a[mt][0] = As[tig][row];
        a[mt][1] = As[tig][row + 8];
        a[mt][2] = As[tig + 4][row];
        a[mt][3] = As[tig + 4][row + 8];
    }
    #pragma unroll
    for (int nt = 0; nt < 4; nt++) {
        int cn = wn + nt * 8 + gid;
        b[nt][0] = Bs[tig][cn];
        b[nt][1] = Bs[tig + 4][cn];
    }
    #pragma unroll
    for (int mt = 0; mt < 4; mt++)
        #pragma unroll
        for (int nt = 0; nt < 4; nt++)
            mma16(acc[mt][nt], a[mt], b[nt]);
}

// fp32 row-major C store (optional bias)
__device__ __forceinline__ void store_tile(
    float* C, size_t ldc, const float* bias,
    float (&acc)[4][4][4], int wm, int wn, int gid, int tig)
{
    #pragma unroll
    for (int mt = 0; mt < 4; mt++) {
        int r0 = wm + mt * 16 + gid, r1 = r0 + 8;
        float b0 = bias ? bias[r0] : 0.0f;
        float b1 = bias ? bias[r1] : 0.0f;
        #pragma unroll
        for (int nt = 0; nt < 4; nt++) {
            int cn = wn + nt * 8 + 2 * tig;
            *(float2*)(C + (size_t)r0 * ldc + cn) =
                make_float2(acc[mt][nt][0] + b0, acc[mt][nt][1] + b0);
            *(float2*)(C + (size_t)r1 * ldc + cn) =
                make_float2(acc[mt][nt][2] + b1, acc[mt][nt][3] + b1);
        }
    }
}

#define WARP_IDX \
    const int tid = threadIdx.x; \
    const int wid = tid >> 5; \
    const int wm = (wid >> 2) * 64, wn = (wid & 3) * 32; \
    const int gid = (tid & 31) >> 2, tig = tid & 3;

// ---------------- panel / x-slab loaders for proj ----------------
__device__ __forceinline__ void ld_panel_half(uint32_t (*wp)[136], const uint32_t* base, int koff, int tid)
{
    int m4 = (tid & 31) * 4, kb = tid >> 5;
    #pragma unroll
    for (int it = 0; it < 8; it++) {
        int k2 = koff + kb + it * 8;
        *(uint4*)&wp[k2][m4] = *(const uint4*)(base + (size_t)k2 * 384 + m4);
    }
}
__device__ __forceinline__ void pf_panel_half(uint4 (&r)[8], const uint32_t* base, int tid)
{
    int m4 = (tid & 31) * 4, kb = tid >> 5;
    #pragma unroll
    for (int it = 0; it < 8; it++)
        r[it] = *(const uint4*)(base + (size_t)(kb + it * 8) * 384 + m4);
}
__device__ __forceinline__ void st_panel_half(uint32_t (*wp)[136], uint4 (&r)[8], int tid)
{
    int m4 = (tid & 31) * 4, kb = tid >> 5;
    #pragma unroll
    for (int it = 0; it < 8; it++)
        *(uint4*)&wp[kb + it * 8][m4] = r[it];
}
__device__ __forceinline__ void load_xs(uint32_t (*xs)[136], const float* xg, int tid)
{
    int c = (tid & 31) * 4, kb = tid >> 5;
    #pragma unroll
    for (int it = 0; it < 16; it++) {
        int k2 = kb + it * 8;
        const float* p = xg + (size_t)(2 * k2) * NN + c;
        float4 u = *(const float4*)p;
        float4 v = *(const float4*)(p + NN);
        xs[k2][c + 0] = bf2(u.x, v.x);
        xs[k2][c + 1] = bf2(u.y, v.y);
        xs[k2][c + 2] = bf2(u.z, v.z);
        xs[k2][c + 3] = bf2(u.w, v.w);
    }
}

// ---------------- Kernel 0: pack weights + zero sums ----------------
__global__ __launch_bounds__(256) void pack_kernel(
    const float* __restrict__ tw, const float* __restrict__ tb,
    const float* __restrict__ pw, const float* __restrict__ pb,
    const float* __restrict__ gw, const float* __restrict__ gb,
    const float* __restrict__ Ww)
{
    int i = blockIdx.x * 256 + threadIdx.x;   // 0 .. 49151
    {
        int k2 = i / 384, m = i - k2 * 384;
        const float* w = (m < 128) ? tw : (m < 256) ? pw : gw;
        float2 v = *(const float2*)(w + (size_t)(m & 127) * 256 + 2 * k2);
        d_Wtp[i] = bf2(v.x, v.y);
    }
    if (i < 64 * 256) {
        int d2 = i >> 8, c = i & 255;
        const float* p = Ww + (size_t)c * 128 + 2 * d2;
        d_Wt2p[i] = bf2(p[0], p[1]);
    }
    if (i < 384) d_bias[i] = (i < 128) ? tb[i] : (i < 256) ? pb[i - 128] : gb[i - 256];
    if (i < 512) d_sums[i] = 0.0f;
}

// ---------------- Kernel 1: fused theta/phi/g projections + M partial ----------------
// 2 n-slices per block; weight panels register-prefetched under the mma stream.
__global__ __launch_bounds__(256, 1) void proj_fused_kernel(const float* __restrict__ x)
{
    extern __shared__ uint32_t sm32[];
    uint32_t (*xs)[136] = (uint32_t(*)[136])sm32;          // 128 rows
    uint32_t (*wp)[136] = xs + 128;                        // 128 rows
    uint32_t (*ps)[136] = wp + 128;                        // 64 rows
    uint32_t (*gs)[136] = ps + 64;                         // 64 rows
    WARP_IDX
    const int b = blockIdx.y, s = blockIdx.x;
    const float* xbase = x + (size_t)b * CC * NN;

    float accM[4][4][4] = {};
    uint4 pf[8];

    // initial: x slab for half 0 + full theta panel
    load_xs(xs, xbase + 2 * s * 128, tid);
    ld_panel_half(wp, d_Wtp, 0, tid);
    ld_panel_half(wp, d_Wtp, 64, tid);
    __syncthreads();

    #pragma unroll
    for (int half = 0; half < 2; half++) {
        const int n0 = (2 * s + half) * 128;

        // ---- theta GEMM (phi lower half prefetched under it) ----
        pf_panel_half(pf, d_Wtp + 128, tid);
        {
            float acc[4][4][4] = {};
            #pragma unroll
            for (int st = 0; st < 16; st++)
                mma_tile16(wp + st * 8, xs + st * 8, acc, wm, wn, gid, tig);
            uint32_t* T = d_theta + (size_t)b * INTER * (NN / 2) + n0 / 2;
            #pragma unroll
            for (int mt = 0; mt < 4; mt++) {
                int r0 = wm + mt * 16 + gid, r1 = r0 + 8;
                float b0 = d_bias[r0], b1 = d_bias[r1];
                #pragma unroll
                for (int nt = 0; nt < 4; nt++) {
                    int cw = (wn + nt * 8 + 2 * tig) >> 1;
                    T[(size_t)r0 * (NN / 2) + cw] = bf2(acc[mt][nt][0] + b0, acc[mt][nt][1] + b0);
                    T[(size_t)r1 * (NN / 2) + cw] = bf2(acc[mt][nt][2] + b1, acc[mt][nt][3] + b1);
                }
            }
        }
        __syncthreads();
        st_panel_half(wp, pf, tid);
        ld_panel_half(wp, d_Wtp + 128, 64, tid);
        __syncthreads();

        // ---- phi GEMM (g lower half prefetched under it) ----
        pf_panel_half(pf, d_Wtp + 256, tid);
        {
            float acc[4][4][4] = {};
            #pragma unroll
            for (int st = 0; st < 16; st++)
                mma_tile16(wp + st * 8, xs + st * 8, acc, wm, wn, gid, tig);
            #pragma unroll
            for (int mt = 0; mt < 4; mt++) {
                int r0 = wm + mt * 16 + gid, r1 = r0 + 8;
                float b0 = d_bias[128 + r0], b1 = d_bias[128 + r1];
                #pragma unroll
                for (int nt = 0; nt < 4; nt++) {
                    int n2 = (wn + nt * 8 + 2 * tig) >> 1;
                    ps[n2][r0] = bf2(acc[mt][nt][0] + b0, acc[mt][nt][1] + b0);
                    ps[n2][r1] = bf2(acc[mt][nt][2] + b1, acc[mt][nt][3] + b1);
                }
            }
        }
        __syncthreads();
        st_panel_half(wp, pf, tid);
        ld_panel_half(wp, d_Wtp + 256, 64, tid);
        __syncthreads();

        // ---- g GEMM (theta lower for next half prefetched under it) ----
        if (half == 0) pf_panel_half(pf, d_Wtp, tid);
        {
            float acc[4][4][4] = {};
            #pragma unroll
            for (int st = 0; st < 16; st++)
                mma_tile16(wp + st * 8, xs + st * 8, acc, wm, wn, gid, tig);
            #pragma unroll
            for (int mt = 0; mt < 4; mt++) {
                int r0 = wm + mt * 16 + gid, r1 = r0 + 8;
                float b0 = d_bias[256 + r0], b1 = d_bias[256 + r1];
                #pragma unroll
                for (int nt = 0; nt < 4; nt++) {
                    int n2 = (wn + nt * 8 + 2 * tig) >> 1;
                    gs[n2][r0] = bf2(acc[mt][nt][0] + b0, acc[mt][nt][1] + b0);
                    gs[n2][r1] = bf2(acc[mt][nt][2] + b1, acc[mt][nt][3] + b1);
                }
            }
        }
        __syncthreads();
        if (half == 0) {
            // next-half theta panel + x slab: issued here, latency hidden by GEMM_M
            st_panel_half(wp, pf, tid);
            ld_panel_half(wp, d_Wtp, 64, tid);
            load_xs(xs, xbase + (n0 + 128), tid);
        }
        // ---- M partial accumulate ----
        #pragma unroll
        for (int s2 = 0; s2 < 8; s2++)
            mma_tile16(ps + s2 * 8, gs + s2 * 8, accM, wm, wn, gid, tig);
        __syncthreads();
    }
    store_tile(d_Mpart + (size_t)(b * MSPLIT + s) * INTER * INTER, INTER,
               nullptr, accM, wm, wn, gid, tig);
}

// ---------------- Kernel 2: Qt[k][c] = sum_d (sum_s Mpart[s][k][d] / N) * Wt2[d][c] ----------------
// mred folded into the A-loader: reduce 8 splits + scale + transpose + cvt to bf16 pairs along d
__global__ __launch_bounds__(256, 2) void q_kernel()
{
    extern __shared__ uint32_t qsm[];
    uint32_t (*As)[136] = (uint32_t(*)[136])qsm;   // 64 rows: [d2][k] pairs along d
    uint32_t (*Bs)[136] = As + 64;                 // 64 rows: [d2][c]
    float acc[4][4][4] = {};
    WARP_IDX
    const int b = blockIdx.y, n0 = blockIdx.x * 128;
    const float* Mp = d_Mpart + (size_t)b * MSPLIT * (INTER * INTER);
    const float inv = 1.0f / (float)NN;
    // A: reduce splits + transpose + cvt (pairs along d)
    {
        int r = tid >> 1, dq = (tid & 1) * 8;      // r = k row, dq = d offset
        #pragma unroll
        for (int st = 0; st < 8; st++) {
            const float* p = Mp + (size_t)r * INTER + st * 16 + dq;
            float a0 = 0.f, a1 = 0.f, a2 = 0.f, a3 = 0.f;
            float a4 = 0.f, a5 = 0.f, a6 = 0.f, a7 = 0.f;
            #pragma unroll
            for (int sp = 0; sp < MSPLIT; sp++) {
                float4 v0 = *(const float4*)(p + (size_t)sp * (INTER * INTER));
                float4 v1 = *(const float4*)(p + (size_t)sp * (INTER * INTER) + 4);
                a0 += v0.x; a1 += v0.y; a2 += v0.z; a3 += v0.w;
                a4 += v1.x; a5 += v1.y; a6 += v1.z; a7 += v1.w;
            }
            int q2 = st * 8 + (tid & 1) * 4;
            As[q2 + 0][r] = bf2(a0 * inv, a1 * inv);
            As[q2 + 1][r] = bf2(a2 * inv, a3 * inv);
            As[q2 + 2][r] = bf2(a4 * inv, a5 * inv);
            As[q2 + 3][r] = bf2(a6 * inv, a7 * inv);
        }
    }
    // B: straight copy slice of pre-packed W_w^T
    {
        int r = tid >> 2, c0 = (tid & 3) * 4;
        #pragma unroll
        for (int it = 0; it < 8; it++) {
            int c = c0 + it * 16;
            *(uint4*)&Bs[r][c] = *(const uint4*)(d_Wt2p + (size_t)r * 256 + n0 + c);
        }
    }
    __syncthreads();
    #pragma unroll
    for (int st = 0; st < 8; st++)
        mma_tile16(As + st * 8, Bs + st * 8, acc, wm, wn, gid, tig);
    store_tile(d_Qt + (size_t)b * INTER * CC + n0, CC, nullptr, acc, wm, wn, gid, tig);
}

// ---------------- bf16-pair loaders for z ----------------
__device__ __forceinline__ void ld_pair_f32(uint32_t (*S)[136], const float* src, size_t ld, int tid)
{
    int k2 = tid >> 5, c = (tid & 31) * 4;
    const float* p = src + (size_t)(2 * k2) * ld + c;
    float4 u = *(const float4*)p;
    float4 v = *(const float4*)(p + ld);
    S[k2][c + 0] = bf2(u.x, v.x);
    S[k2][c + 1] = bf2(u.y, v.y);
    S[k2][c + 2] = bf2(u.z, v.z);
    S[k2][c + 3] = bf2(u.w, v.w);
}
__device__ __forceinline__ void ld_pair_bf(uint32_t (*S)[136], const uint32_t* src, size_t ldw, int tid)
{
    int k2 = tid >> 5, c2 = (tid & 31) * 2;
    const uint32_t* p = src + (size_t)(2 * k2) * ldw + c2;
    uint32_t w00 = p[0], w01 = p[1];
    uint32_t w10 = p[ldw], w11 = p[ldw + 1];
    S[k2][c2 * 2 + 0] = __byte_perm(w00, w10, 0x5410);
    S[k2][c2 * 2 + 1] = __byte_perm(w00, w10, 0x7632);
    S[k2][c2 * 2 + 2] = __byte_perm(w01, w11, 0x5410);
    S[k2][c2 * 2 + 3] = __byte_perm(w01, w11, 0x7632);
}

// ---------------- Kernel 3: z = Q @ theta + W_b (bf16 out) + BN partial stats ----------------
__global__ __launch_bounds__(256, 2) void z_kernel(const float* __restrict__ W_b)
{
    extern __shared__ uint32_t zsm[];
    uint32_t (*As)[136] = (uint32_t(*)[136])zsm;   // 64 rows: [k2][c]
    uint32_t (*Bs)[136] = As + 64;                 // 64 rows: [k2][n]
    float acc[4][4][4] = {};
    WARP_IDX
    const int b = blockIdx.z, m0 = blockIdx.y * 128, n0 = blockIdx.x * 128;
    const float* A = d_Qt + (size_t)b * INTER * CC + m0;            // [k][c]
    const uint32_t* B = d_theta + (size_t)b * INTER * (NN / 2) + n0 / 2;
    #pragma unroll
    for (int st = 0; st < 8; st++) {
        ld_pair_f32(As + st * 8, A + (size_t)st * 16 * CC, CC, tid);
        ld_pair_bf(Bs + st * 8, B + (size_t)st * 16 * (NN / 2), NN / 2, tid);
    }
    __syncthreads();
    #pragma unroll
    for (int st = 0; st < 8; st++)
        mma_tile16(As + st * 8, Bs + st * 8, acc, wm, wn, gid, tig);

    uint32_t* zb = d_zb + ((size_t)b * CC + m0) * (NN / 2) + n0 / 2;
    #pragma unroll
    for (int mt = 0; mt < 4; mt++) {
        int r0 = wm + mt * 16 + gid, r1 = r0 + 8;
        float b0 = W_b[m0 + r0], b1 = W_b[m0 + r1];
        float s0 = 0.f, q0 = 0.f, s1 = 0.f, q1 = 0.f;
        #pragma unroll
        for (int nt = 0; nt < 4; nt++) {
            int cn = wn + nt * 8 + 2 * tig;
            float v00 = acc[mt][nt][0] + b0, v01 = acc[mt][nt][1] + b0;
            float v10 = acc[mt][nt][2] + b1, v11 = acc[mt][nt][3] + b1;
            zb[(size_t)r0 * (NN / 2) + (cn >> 1)] = bf2(v00, v01);
            zb[(size_t)r1 * (NN / 2) + (cn >> 1)] = bf2(v10, v11);
            s0 += v00 + v01;  q0 += v00 * v00 + v01 * v01;
            s1 += v10 + v11;  q1 += v10 * v10 + v11 * v11;
        }
        s0 += __shfl_xor_sync(~0u, s0, 1); s0 += __shfl_xor_sync(~0u, s0, 2);
        q0 += __shfl_xor_sync(~0u, q0, 1); q0 += __shfl_xor_sync(~0u, q0, 2);
        s1 += __shfl_xor_sync(~0u, s1, 1); s1 += __shfl_xor_sync(~0u, s1, 2);
        q1 += __shfl_xor_sync(~0u, q1, 1); q1 += __shfl_xor_sync(~0u, q1, 2);
        if (tig == 0) {
            atomicAdd(&d_sums[m0 + r0], s0);       atomicAdd(&d_sums[256 + m0 + r0], q0);
            atomicAdd(&d_sums[m0 + r1], s1);       atomicAdd(&d_sums[256 + m0 + r1], q1);
        }
    }
}

// ---------------- Kernel 4: out = z*scale + shift + x (stats finalized inline) ----------------
__global__ __launch_bounds__(256) void bn_apply_kernel(
    const float* __restrict__ x, float* __restrict__ out,
    const float* __restrict__ gamma, const float* __restrict__ beta)
{
    const size_t i = (size_t)blockIdx.x * 256 + threadIdx.x;  // float4 index
    const int c = (int)((i >> 9) & (CC - 1));
    const float inv = 1.0f / (float)(BB * NN);
    float mean = d_sums[c] * inv;
    float var  = d_sums[256 + c] * inv - mean * mean;
    float sc   = gamma[c] * rsqrtf(var + 1e-5f);
    float sh   = beta[c] - mean * sc;
    uint2 zp = ((const uint2*)d_zb)[i];
    float4 xv = ((const float4*)x)[i];
    float z0 = __uint_as_float(zp.x << 16);
    float z1 = __uint_as_float(zp.x & 0xffff0000u);
    float z2 = __uint_as_float(zp.y << 16);
    float z3 = __uint_as_float(zp.y & 0xffff0000u);
    float4 o;
    o.x = z0 * sc + sh + xv.x;
    o.y = z1 * sc + sh + xv.y;
    o.z = z2 * sc + sh + xv.z;
    o.w = z3 * sc + sh + xv.w;
    ((float4*)out)[i] = o;
}

// ---------------- launch ----------------
extern "C" void kernel_launch(void* const* d_in, const int* in_sizes, int n_in,
                              void* d_out, int out_size)
{
    const float* x       = (const float*)d_in[0];
    const float* g_w     = (const float*)d_in[1];
    const float* g_b     = (const float*)d_in[2];
    const float* theta_w = (const float*)d_in[3];
    const float* theta_b = (const float*)d_in[4];
    const float* phi_w   = (const float*)d_in[5];
    const float* phi_b   = (const float*)d_in[6];
    const float* W_w     = (const float*)d_in[7];
    const float* W_b     = (const float*)d_in[8];
    const float* gamma   = (const float*)d_in[9];
    const float* beta    = (const float*)d_in[10];
    float* out = (float*)d_out;

    const int pf_smem = (128 + 128 + 64 + 64) * 136 * 4;   // 208896
    const int q_smem  = (64 + 64) * 136 * 4;               // 69632
    const int z_smem  = (64 + 64) * 136 * 4;               // 69632
    static bool attr_set = false;
    if (!attr_set) {
        cudaFuncSetAttribute(proj_fused_kernel, cudaFuncAttributeMaxDynamicSharedMemorySize, pf_smem);
        cudaFuncSetAttribute(q_kernel, cudaFuncAttributeMaxDynamicSharedMemorySize, q_smem);
        cudaFuncSetAttribute(z_kernel, cudaFuncAttributeMaxDynamicSharedMemorySize, z_smem);
        attr_set = true;
    }

    pack_kernel      <<<192, 256>>>(theta_w, theta_b, phi_w, phi_b, g_w, g_b, W_w);
    proj_fused_kernel<<<dim3(MSPLIT, BB), 256, pf_smem>>>(x);
    q_kernel         <<<dim3(2, BB), 256, q_smem>>>();
    z_kernel         <<<dim3(NN / 128, 2, BB), 256, z_smem>>>(W_b);
    bn_apply_kernel  <<<(size_t)(BB * CC * NN) / 4 / 256, 256>>>(x, out, gamma, beta);
}

// round 10
// speedup vs baseline: 1.0336x; 1.0336x over previous
#include <cuda_runtime.h>
#include <cstdint>

#define BB    16
#define CC    256
#define INTER 128
#define NN    2048
#define MSPLIT 8            // two 128-n slices per block

// ---------------- scratch ----------------
__device__ uint32_t d_Wtp [128 * 384];                 // bf16 pairs along k: [k2][m], m = theta|phi|g
__device__ uint32_t d_Wt2p[64 * 256];                  // W_w^T bf16 pairs along d: [d2][c]
__device__ float    d_bias[384];
__device__ uint32_t d_theta[(size_t)BB * INTER * (NN / 2)];   // bf16 pairs along n: [b][k][n2]
__device__ float    d_Mpart[(size_t)BB * MSPLIT * INTER * INTER];
__device__ float    d_Mred [(size_t)BB * INTER * INTER];
__device__ float    d_Qt   [(size_t)BB * INTER * CC];  // [b][k][c]
__device__ uint32_t d_zb   [(size_t)BB * CC * (NN / 2)];      // z as bf16 pairs along n
__device__ float    d_sums [512];

// ---------------- helpers ----------------
__device__ __forceinline__ uint32_t bf2(float lo, float hi) {
    uint32_t r; asm("cvt.rn.bf16x2.f32 %0,%1,%2;" : "=r"(r) : "f"(hi), "f"(lo));
    return r;
}
__device__ __forceinline__ void mma16(float* c, const uint32_t* a, const uint32_t* b) {
    asm volatile("mma.sync.aligned.m16n8k16.row.col.f32.bf16.bf16.f32 "
        "{%0,%1,%2,%3},{%4,%5,%6,%7},{%8,%9},{%0,%1,%2,%3};"
        : "+f"(c[0]), "+f"(c[1]), "+f"(c[2]), "+f"(c[3])
        : "r"(a[0]), "r"(a[1]), "r"(a[2]), "r"(a[3]), "r"(b[0]), "r"(b[1]));
}

// ---------------- bf16 mma over one 16-k slab (slabs are [8][136]) ----------------
__device__ __forceinline__ void mma_tile16(
    const uint32_t (*As)[136], const uint32_t (*Bs)[136],
    float (&acc)[4][4][4], int wm, int wn, int gid, int tig)
{
    uint32_t a[4][4], b[4][2];
    #pragma unroll
    for (int mt = 0; mt < 4; mt++) {
        int row = wm + mt * 16 + gid;
        a[mt][0] = As[tig][row];
        a[mt][1] = As[tig][row + 8];
        a[mt][2] = As[tig + 4][row];
        a[mt][3] = As[tig + 4][row + 8];
    }
    #pragma unroll
    for (int nt = 0; nt < 4; nt++) {
        int cn = wn + nt * 8 + gid;
        b[nt][0] = Bs[tig][cn];
        b[nt][1] = Bs[tig + 4][cn];
    }
    #pragma unroll
    for (int mt = 0; mt < 4; mt++)
        #pragma unroll
        for (int nt = 0; nt < 4; nt++)
            mma16(acc[mt][nt], a[mt], b[nt]);
}

// fp32 row-major C store (optional bias)
__device__ __forceinline__ void store_tile(
    float* C, size_t ldc, const float* bias,
    float (&acc)[4][4][4], int wm, int wn, int gid, int tig)
{
    #pragma unroll
    for (int mt = 0; mt < 4; mt++) {
        int r0 = wm + mt * 16 + gid, r1 = r0 + 8;
        float b0 = bias ? bias[r0] : 0.0f;
        float b1 = bias ? bias[r1] : 0.0f;
        #pragma unroll
        for (int nt = 0; nt < 4; nt++) {
            int cn = wn + nt * 8 + 2 * tig;
            *(float2*)(C + (size_t)r0 * ldc + cn) =
                make_float2(acc[mt][nt][0] + b0, acc[mt][nt][1] + b0);
            *(float2*)(C + (size_t)r1 * ldc + cn) =
                make_float2(acc[mt][nt][2] + b1, acc[mt][nt][3] + b1);
        }
    }
}

#define WARP_IDX \
    const int tid = threadIdx.x; \
    const int wid = tid >> 5; \
    const int wm = (wid >> 2) * 64, wn = (wid & 3) * 32; \
    const int gid = (tid & 31) >> 2, tig = tid & 3;

// ---------------- panel / x-slab loaders for proj ----------------
__device__ __forceinline__ void ld_panel_half(uint32_t (*wp)[136], const uint32_t* base, int koff, int tid)
{
    int m4 = (tid & 31) * 4, kb = tid >> 5;
    #pragma unroll
    for (int it = 0; it < 8; it++) {
        int k2 = koff + kb + it * 8;
        *(uint4*)&wp[k2][m4] = *(const uint4*)(base + (size_t)k2 * 384 + m4);
    }
}
__device__ __forceinline__ void pf_panel_half(uint4 (&r)[8], const uint32_t* base, int tid)
{
    int m4 = (tid & 31) * 4, kb = tid >> 5;
    #pragma unroll
    for (int it = 0; it < 8; it++)
        r[it] = *(const uint4*)(base + (size_t)(kb + it * 8) * 384 + m4);
}
__device__ __forceinline__ void st_panel_half(uint32_t (*wp)[136], uint4 (&r)[8], int tid)
{
    int m4 = (tid & 31) * 4, kb = tid >> 5;
    #pragma unroll
    for (int it = 0; it < 8; it++)
        *(uint4*)&wp[kb + it * 8][m4] = r[it];
}
__device__ __forceinline__ void load_xs(uint32_t (*xs)[136], const float* xg, int tid)
{
    int c = (tid & 31) * 4, kb = tid >> 5;
    #pragma unroll
    for (int it = 0; it < 16; it++) {
        int k2 = kb + it * 8;
        const float* p = xg + (size_t)(2 * k2) * NN + c;
        float4 u = *(const float4*)p;
        float4 v = *(const float4*)(p + NN);
        xs[k2][c + 0] = bf2(u.x, v.x);
        xs[k2][c + 1] = bf2(u.y, v.y);
        xs[k2][c + 2] = bf2(u.z, v.z);
        xs[k2][c + 3] = bf2(u.w, v.w);
    }
}

// ---------------- Kernel 0: pack weights + zero sums ----------------
__global__ __launch_bounds__(256) void pack_kernel(
    const float* __restrict__ tw, const float* __restrict__ tb,
    const float* __restrict__ pw, const float* __restrict__ pb,
    const float* __restrict__ gw, const float* __restrict__ gb,
    const float* __restrict__ Ww)
{
    int i = blockIdx.x * 256 + threadIdx.x;   // 0 .. 49151
    {
        int k2 = i / 384, m = i - k2 * 384;
        const float* w = (m < 128) ? tw : (m < 256) ? pw : gw;
        float2 v = *(const float2*)(w + (size_t)(m & 127) * 256 + 2 * k2);
        d_Wtp[i] = bf2(v.x, v.y);
    }
    if (i < 64 * 256) {
        int d2 = i >> 8, c = i & 255;
        const float* p = Ww + (size_t)c * 128 + 2 * d2;
        d_Wt2p[i] = bf2(p[0], p[1]);
    }
    if (i < 384) d_bias[i] = (i < 128) ? tb[i] : (i < 256) ? pb[i - 128] : gb[i - 256];
    if (i < 512) d_sums[i] = 0.0f;
}

// ---------------- Kernel 1: fused theta/phi/g projections + M partial ----------------
// 2 n-slices per block; weight panels register-prefetched under the mma stream.
__global__ __launch_bounds__(256, 1) void proj_fused_kernel(const float* __restrict__ x)
{
    extern __shared__ uint32_t sm32[];
    uint32_t (*xs)[136] = (uint32_t(*)[136])sm32;          // 128 rows
    uint32_t (*wp)[136] = xs + 128;                        // 128 rows
    uint32_t (*ps)[136] = wp + 128;                        // 64 rows
    uint32_t (*gs)[136] = ps + 64;                         // 64 rows
    WARP_IDX
    const int b = blockIdx.y, s = blockIdx.x;
    const float* xbase = x + (size_t)b * CC * NN;

    float accM[4][4][4] = {};
    uint4 pf[8];

    // initial: x slab for half 0 + full theta panel
    load_xs(xs, xbase + 2 * s * 128, tid);
    ld_panel_half(wp, d_Wtp, 0, tid);
    ld_panel_half(wp, d_Wtp, 64, tid);
    __syncthreads();

    #pragma unroll
    for (int half = 0; half < 2; half++) {
        const int n0 = (2 * s + half) * 128;

        // ---- theta GEMM (phi lower half prefetched under it) ----
        pf_panel_half(pf, d_Wtp + 128, tid);
        {
            float acc[4][4][4] = {};
            #pragma unroll
            for (int st = 0; st < 16; st++)
                mma_tile16(wp + st * 8, xs + st * 8, acc, wm, wn, gid, tig);
            uint32_t* T = d_theta + (size_t)b * INTER * (NN / 2) + n0 / 2;
            #pragma unroll
            for (int mt = 0; mt < 4; mt++) {
                int r0 = wm + mt * 16 + gid, r1 = r0 + 8;
                float b0 = d_bias[r0], b1 = d_bias[r1];
                #pragma unroll
                for (int nt = 0; nt < 4; nt++) {
                    int cw = (wn + nt * 8 + 2 * tig) >> 1;
                    T[(size_t)r0 * (NN / 2) + cw] = bf2(acc[mt][nt][0] + b0, acc[mt][nt][1] + b0);
                    T[(size_t)r1 * (NN / 2) + cw] = bf2(acc[mt][nt][2] + b1, acc[mt][nt][3] + b1);
                }
            }
        }
        __syncthreads();
        st_panel_half(wp, pf, tid);
        ld_panel_half(wp, d_Wtp + 128, 64, tid);
        __syncthreads();

        // ---- phi GEMM (g lower half prefetched under it) ----
        pf_panel_half(pf, d_Wtp + 256, tid);
        {
            float acc[4][4][4] = {};
            #pragma unroll
            for (int st = 0; st < 16; st++)
                mma_tile16(wp + st * 8, xs + st * 8, acc, wm, wn, gid, tig);
            #pragma unroll
            for (int mt = 0; mt < 4; mt++) {
                int r0 = wm + mt * 16 + gid, r1 = r0 + 8;
                float b0 = d_bias[128 + r0], b1 = d_bias[128 + r1];
                #pragma unroll
                for (int nt = 0; nt < 4; nt++) {
                    int n2 = (wn + nt * 8 + 2 * tig) >> 1;
                    ps[n2][r0] = bf2(acc[mt][nt][0] + b0, acc[mt][nt][1] + b0);
                    ps[n2][r1] = bf2(acc[mt][nt][2] + b1, acc[mt][nt][3] + b1);
                }
            }
        }
        __syncthreads();
        st_panel_half(wp, pf, tid);
        ld_panel_half(wp, d_Wtp + 256, 64, tid);
        __syncthreads();

        // ---- g GEMM (theta lower for next half prefetched under it) ----
        if (half == 0) pf_panel_half(pf, d_Wtp, tid);
        {
            float acc[4][4][4] = {};
            #pragma unroll
            for (int st = 0; st < 16; st++)
                mma_tile16(wp + st * 8, xs + st * 8, acc, wm, wn, gid, tig);
            #pragma unroll
            for (int mt = 0; mt < 4; mt++) {
                int r0 = wm + mt * 16 + gid, r1 = r0 + 8;
                float b0 = d_bias[256 + r0], b1 = d_bias[256 + r1];
                #pragma unroll
                for (int nt = 0; nt < 4; nt++) {
                    int n2 = (wn + nt * 8 + 2 * tig) >> 1;
                    gs[n2][r0] = bf2(acc[mt][nt][0] + b0, acc[mt][nt][1] + b0);
                    gs[n2][r1] = bf2(acc[mt][nt][2] + b1, acc[mt][nt][3] + b1);
                }
            }
        }
        __syncthreads();
        if (half == 0) {
            // next-half theta panel + x slab: issued here, latency hidden by GEMM_M
            st_panel_half(wp, pf, tid);
            ld_panel_half(wp, d_Wtp, 64, tid);
            load_xs(xs, xbase + (n0 + 128), tid);
        }
        // ---- M partial accumulate ----
        #pragma unroll
        for (int s2 = 0; s2 < 8; s2++)
            mma_tile16(ps + s2 * 8, gs + s2 * 8, accM, wm, wn, gid, tig);
        __syncthreads();
    }
    store_tile(d_Mpart + (size_t)(b * MSPLIT + s) * INTER * INTER, INTER,
               nullptr, accM, wm, wn, gid, tig);
}

// ---------------- Kernel 2: reduce split partials, scale 1/N ----------------
__global__ __launch_bounds__(256) void mred_kernel()
{
    const int i = blockIdx.x * 256 + threadIdx.x;   // float2 index, 131072 total
    const int b = i >> 13, r = i & 8191;
    const float2* p = (const float2*)(d_Mpart + (size_t)b * MSPLIT * 16384) + r;
    float2 a = make_float2(0.f, 0.f);
    #pragma unroll
    for (int sp = 0; sp < MSPLIT; sp++) {
        float2 v = p[(size_t)sp * 8192];
        a.x += v.x; a.y += v.y;
    }
    const float inv = 1.0f / (float)NN;
    ((float2*)(d_Mred + (size_t)b * 16384))[r] = make_float2(a.x * inv, a.y * inv);
}

// ---------------- Kernel 3: Qt[k][c] = sum_d Mred[k][d] * Wt2[d][c]  (bf16) ----------------
__global__ __launch_bounds__(256, 2) void q_kernel()
{
    extern __shared__ uint32_t qsm[];
    uint32_t (*As)[136] = (uint32_t(*)[136])qsm;   // 64 rows: [d2][k] pairs along d
    uint32_t (*Bs)[136] = As + 64;                 // 64 rows: [d2][c]
    float acc[4][4][4] = {};
    WARP_IDX
    const int b = blockIdx.y, n0 = blockIdx.x * 128;
    const float* M = d_Mred + (size_t)b * INTER * INTER;
    // A: transpose + cvt (pairs along d)
    {
        int r = tid >> 1, dq = (tid & 1) * 8;
        #pragma unroll
        for (int st = 0; st < 8; st++) {
            const float* p = M + (size_t)r * INTER + st * 16 + dq;
            float4 v0 = *(const float4*)p, v1 = *(const float4*)(p + 4);
            int q2 = st * 8 + (tid & 1) * 4;
            As[q2 + 0][r] = bf2(v0.x, v0.y);
            As[q2 + 1][r] = bf2(v0.z, v0.w);
            As[q2 + 2][r] = bf2(v1.x, v1.y);
            As[q2 + 3][r] = bf2(v1.z, v1.w);
        }
    }
    // B: straight copy slice of pre-packed W_w^T
    {
        int r = tid >> 2, c0 = (tid & 3) * 4;
        #pragma unroll
        for (int it = 0; it < 8; it++) {
            int c = c0 + it * 16;
            *(uint4*)&Bs[r][c] = *(const uint4*)(d_Wt2p + (size_t)r * 256 + n0 + c);
        }
    }
    __syncthreads();
    #pragma unroll
    for (int st = 0; st < 8; st++)
        mma_tile16(As + st * 8, Bs + st * 8, acc, wm, wn, gid, tig);
    store_tile(d_Qt + (size_t)b * INTER * CC + n0, CC, nullptr, acc, wm, wn, gid, tig);
}

// ---------------- bf16-pair loaders for z ----------------
__device__ __forceinline__ void ld_pair_f32(uint32_t (*S)[136], const float* src, size_t ld, int tid)
{
    int k2 = tid >> 5, c = (tid & 31) * 4;
    const float* p = src + (size_t)(2 * k2) * ld + c;
    float4 u = *(const float4*)p;
    float4 v = *(const float4*)(p + ld);
    S[k2][c + 0] = bf2(u.x, v.x);
    S[k2][c + 1] = bf2(u.y, v.y);
    S[k2][c + 2] = bf2(u.z, v.z);
    S[k2][c + 3] = bf2(u.w, v.w);
}
__device__ __forceinline__ void ld_pair_bf(uint32_t (*S)[136], const uint32_t* src, size_t ldw, int tid)
{
    int k2 = tid >> 5, c2 = (tid & 31) * 2;
    const uint32_t* p = src + (size_t)(2 * k2) * ldw + c2;
    uint32_t w00 = p[0], w01 = p[1];
    uint32_t w10 = p[ldw], w11 = p[ldw + 1];
    S[k2][c2 * 2 + 0] = __byte_perm(w00, w10, 0x5410);
    S[k2][c2 * 2 + 1] = __byte_perm(w00, w10, 0x7632);
    S[k2][c2 * 2 + 2] = __byte_perm(w01, w11, 0x5410);
    S[k2][c2 * 2 + 3] = __byte_perm(w01, w11, 0x7632);
}

// ---------------- z epilogue: bf16 store + BN partial stats ----------------
__device__ __forceinline__ void z_epilogue(
    float (&acc)[4][4][4], uint32_t* zb, const float* __restrict__ W_b, int m0,
    int wm, int wn, int gid, int tig)
{
    #pragma unroll
    for (int mt = 0; mt < 4; mt++) {
        int r0 = wm + mt * 16 + gid, r1 = r0 + 8;
        float b0 = W_b[m0 + r0], b1 = W_b[m0 + r1];
        float s0 = 0.f, q0 = 0.f, s1 = 0.f, q1 = 0.f;
        #pragma unroll
        for (int nt = 0; nt < 4; nt++) {
            int cn = wn + nt * 8 + 2 * tig;
            float v00 = acc[mt][nt][0] + b0, v01 = acc[mt][nt][1] + b0;
            float v10 = acc[mt][nt][2] + b1, v11 = acc[mt][nt][3] + b1;
            zb[(size_t)r0 * (NN / 2) + (cn >> 1)] = bf2(v00, v01);
            zb[(size_t)r1 * (NN / 2) + (cn >> 1)] = bf2(v10, v11);
            s0 += v00 + v01;  q0 += v00 * v00 + v01 * v01;
            s1 += v10 + v11;  q1 += v10 * v10 + v11 * v11;
        }
        s0 += __shfl_xor_sync(~0u, s0, 1); s0 += __shfl_xor_sync(~0u, s0, 2);
        q0 += __shfl_xor_sync(~0u, q0, 1); q0 += __shfl_xor_sync(~0u, q0, 2);
        s1 += __shfl_xor_sync(~0u, s1, 1); s1 += __shfl_xor_sync(~0u, s1, 2);
        q1 += __shfl_xor_sync(~0u, q1, 1); q1 += __shfl_xor_sync(~0u, q1, 2);
        if (tig == 0) {
            atomicAdd(&d_sums[m0 + r0], s0);       atomicAdd(&d_sums[256 + m0 + r0], q0);
            atomicAdd(&d_sums[m0 + r1], s1);       atomicAdd(&d_sums[256 + m0 + r1], q1);
        }
    }
}

// ---------------- Kernel 4: z = Q @ theta + W_b over TWO n-tiles (theta double-buffered) ----------------
__global__ __launch_bounds__(256, 2) void z_kernel(const float* __restrict__ W_b)
{
    extern __shared__ uint32_t zsm[];
    uint32_t (*As)[136] = (uint32_t(*)[136])zsm;   // 64 rows: [k2][c]
    uint32_t (*B0)[136] = As + 64;                 // 64 rows: [k2][n] tile 0
    uint32_t (*B1)[136] = B0 + 64;                 // 64 rows: [k2][n] tile 1
    float acc[4][4][4] = {};
    WARP_IDX
    const int b = blockIdx.z, m0 = blockIdx.y * 128, n0 = blockIdx.x * 256;
    const float* A = d_Qt + (size_t)b * INTER * CC + m0;            // [k][c]
    const uint32_t* B = d_theta + (size_t)b * INTER * (NN / 2) + n0 / 2;
    // stage 0: A + theta tile 0
    #pragma unroll
    for (int st = 0; st < 8; st++) {
        ld_pair_f32(As + st * 8, A + (size_t)st * 16 * CC, CC, tid);
        ld_pair_bf(B0 + st * 8, B + (size_t)st * 16 * (NN / 2), NN / 2, tid);
    }
    __syncthreads();
    // issue theta tile 1 loads (latency hidden under tile-0 mma + epilogue)
    #pragma unroll
    for (int st = 0; st < 8; st++)
        ld_pair_bf(B1 + st * 8, B + (size_t)st * 16 * (NN / 2) + 64, NN / 2, tid);
    // tile 0 mma + epilogue
    #pragma unroll
    for (int st = 0; st < 8; st++)
        mma_tile16(As + st * 8, B0 + st * 8, acc, wm, wn, gid, tig);
    z_epilogue(acc, d_zb + ((size_t)b * CC + m0) * (NN / 2) + n0 / 2, W_b, m0, wm, wn, gid, tig);
    __syncthreads();
    // tile 1
    #pragma unroll
    for (int mt = 0; mt < 4; mt++)
        #pragma unroll
        for (int nt = 0; nt < 4; nt++)
            #pragma unroll
            for (int v = 0; v < 4; v++) acc[mt][nt][v] = 0.0f;
    #pragma unroll
    for (int st = 0; st < 8; st++)
        mma_tile16(As + st * 8, B1 + st * 8, acc, wm, wn, gid, tig);
    z_epilogue(acc, d_zb + ((size_t)b * CC + m0) * (NN / 2) + (n0 + 128) / 2, W_b, m0, wm, wn, gid, tig);
}

// ---------------- Kernel 5: out = z*scale + shift + x (stats finalized inline) ----------------
__global__ __launch_bounds__(256) void bn_apply_kernel(
    const float* __restrict__ x, float* __restrict__ out,
    const float* __restrict__ gamma, const float* __restrict__ beta)
{
    const size_t i = (size_t)blockIdx.x * 256 + threadIdx.x;  // float4 index
    const int c = (int)((i >> 9) & (CC - 1));
    const float inv = 1.0f / (float)(BB * NN);
    float mean = d_sums[c] * inv;
    float var  = d_sums[256 + c] * inv - mean * mean;
    float sc   = gamma[c] * rsqrtf(var + 1e-5f);
    float sh   = beta[c] - mean * sc;
    uint2 zp = ((const uint2*)d_zb)[i];
    float4 xv = ((const float4*)x)[i];
    float z0 = __uint_as_float(zp.x << 16);
    float z1 = __uint_as_float(zp.x & 0xffff0000u);
    float z2 = __uint_as_float(zp.y << 16);
    float z3 = __uint_as_float(zp.y & 0xffff0000u);
    float4 o;
    o.x = z0 * sc + sh + xv.x;
    o.y = z1 * sc + sh + xv.y;
    o.z = z2 * sc + sh + xv.z;
    o.w = z3 * sc + sh + xv.w;
    ((float4*)out)[i] = o;
}

// ---------------- launch ----------------
extern "C" void kernel_launch(void* const* d_in, const int* in_sizes, int n_in,
                              void* d_out, int out_size)
{
    const float* x       = (const float*)d_in[0];
    const float* g_w     = (const float*)d_in[1];
    const float* g_b     = (const float*)d_in[2];
    const float* theta_w = (const float*)d_in[3];
    const float* theta_b = (const float*)d_in[4];
    const float* phi_w   = (const float*)d_in[5];
    const float* phi_b   = (const float*)d_in[6];
    const float* W_w     = (const float*)d_in[7];
    const float* W_b     = (const float*)d_in[8];
    const float* gamma   = (const float*)d_in[9];
    const float* beta    = (const float*)d_in[10];
    float* out = (float*)d_out;

    const int pf_smem = (128 + 128 + 64 + 64) * 136 * 4;   // 208896
    const int q_smem  = (64 + 64) * 136 * 4;               // 69632
    const int z_smem  = (64 + 64 + 64) * 136 * 4;          // 104448
    static bool attr_set = false;
    if (!attr_set) {
        cudaFuncSetAttribute(proj_fused_kernel, cudaFuncAttributeMaxDynamicSharedMemorySize, pf_smem);
        cudaFuncSetAttribute(q_kernel, cudaFuncAttributeMaxDynamicSharedMemorySize, q_smem);
        cudaFuncSetAttribute(z_kernel, cudaFuncAttributeMaxDynamicSharedMemorySize, z_smem);
        attr_set = true;
    }

    pack_kernel      <<<192, 256>>>(theta_w, theta_b, phi_w, phi_b, g_w, g_b, W_w);
    proj_fused_kernel<<<dim3(MSPLIT, BB), 256, pf_smem>>>(x);
    mred_kernel      <<<512, 256>>>();
    q_kernel         <<<dim3(2, BB), 256, q_smem>>>();
    z_kernel         <<<dim3(NN / 256, 2, BB), 256, z_smem>>>(W_b);
    bn_apply_kernel  <<<(size_t)(BB * CC * NN) / 4 / 256, 256>>>(x, out, gamma, beta);
}

// round 11
// speedup vs baseline: 1.1084x; 1.0724x over previous
#include <cuda_runtime.h>
#include <cstdint>

#define BB    16
#define CC    256
#define INTER 128
#define NN    2048
#define MSPLIT 8            // two 128-n slices per block

// ---------------- scratch ----------------
__device__ uint32_t d_Wtp [128 * 384];                 // bf16 pairs along k: [k2][m], m = theta|phi|g
__device__ uint32_t d_Wt2p[64 * 256];                  // W_w^T bf16 pairs along d: [d2][c]
__device__ float    d_bias[384];
__device__ uint32_t d_theta[(size_t)BB * INTER * (NN / 2)];   // bf16 pairs along n: [b][k][n2]
__device__ float    d_Mred [(size_t)BB * INTER * INTER];      // atomically accumulated M (pre-1/N)
__device__ float    d_Qt   [(size_t)BB * INTER * CC];  // [b][k][c]
__device__ uint32_t d_zb   [(size_t)BB * CC * (NN / 2)];      // z as bf16 pairs along n
__device__ float    d_sums [512];

// ---------------- helpers ----------------
__device__ __forceinline__ uint32_t bf2(float lo, float hi) {
    uint32_t r; asm("cvt.rn.bf16x2.f32 %0,%1,%2;" : "=r"(r) : "f"(hi), "f"(lo));
    return r;
}
__device__ __forceinline__ void mma16(float* c, const uint32_t* a, const uint32_t* b) {
    asm volatile("mma.sync.aligned.m16n8k16.row.col.f32.bf16.bf16.f32 "
        "{%0,%1,%2,%3},{%4,%5,%6,%7},{%8,%9},{%0,%1,%2,%3};"
        : "+f"(c[0]), "+f"(c[1]), "+f"(c[2]), "+f"(c[3])
        : "r"(a[0]), "r"(a[1]), "r"(a[2]), "r"(a[3]), "r"(b[0]), "r"(b[1]));
}

// ---------------- bf16 mma over one 16-k slab (slabs are [8][136]) ----------------
__device__ __forceinline__ void mma_tile16(
    const uint32_t (*As)[136], const uint32_t (*Bs)[136],
    float (&acc)[4][4][4], int wm, int wn, int gid, int tig)
{
    uint32_t a[4][4], b[4][2];
    #pragma unroll
    for (int mt = 0; mt < 4; mt++) {
        int row = wm + mt * 16 + gid;
        a[mt][0] = As[tig][row];
        a[mt][1] = As[tig][row + 8];
        a[mt][2] = As[tig + 4][row];
        a[mt][3] = As[tig + 4][row + 8];
    }
    #pragma unroll
    for (int nt = 0; nt < 4; nt++) {
        int cn = wn + nt * 8 + gid;
        b[nt][0] = Bs[tig][cn];
        b[nt][1] = Bs[tig + 4][cn];
    }
    #pragma unroll
    for (int mt = 0; mt < 4; mt++)
        #pragma unroll
        for (int nt = 0; nt < 4; nt++)
            mma16(acc[mt][nt], a[mt], b[nt]);
}

// fp32 row-major C store (optional bias)
__device__ __forceinline__ void store_tile(
    float* C, size_t ldc, const float* bias,
    float (&acc)[4][4][4], int wm, int wn, int gid, int tig)
{
    #pragma unroll
    for (int mt = 0; mt < 4; mt++) {
        int r0 = wm + mt * 16 + gid, r1 = r0 + 8;
        float b0 = bias ? bias[r0] : 0.0f;
        float b1 = bias ? bias[r1] : 0.0f;
        #pragma unroll
        for (int nt = 0; nt < 4; nt++) {
            int cn = wn + nt * 8 + 2 * tig;
            *(float2*)(C + (size_t)r0 * ldc + cn) =
                make_float2(acc[mt][nt][0] + b0, acc[mt][nt][1] + b0);
            *(float2*)(C + (size_t)r1 * ldc + cn) =
                make_float2(acc[mt][nt][2] + b1, acc[mt][nt][3] + b1);
        }
    }
}

// atomic-accumulate C tile into gmem (for split-K M reduction)
__device__ __forceinline__ void red_tile(
    float* C, size_t ldc,
    float (&acc)[4][4][4], int wm, int wn, int gid, int tig)
{
    #pragma unroll
    for (int mt = 0; mt < 4; mt++) {
        int r0 = wm + mt * 16 + gid, r1 = r0 + 8;
        #pragma unroll
        for (int nt = 0; nt < 4; nt++) {
            int cn = wn + nt * 8 + 2 * tig;
            atomicAdd(C + (size_t)r0 * ldc + cn,     acc[mt][nt][0]);
            atomicAdd(C + (size_t)r0 * ldc + cn + 1, acc[mt][nt][1]);
            atomicAdd(C + (size_t)r1 * ldc + cn,     acc[mt][nt][2]);
            atomicAdd(C + (size_t)r1 * ldc + cn + 1, acc[mt][nt][3]);
        }
    }
}

#define WARP_IDX \
    const int tid = threadIdx.x; \
    const int wid = tid >> 5; \
    const int wm = (wid >> 2) * 64, wn = (wid & 3) * 32; \
    const int gid = (tid & 31) >> 2, tig = tid & 3;

// ---------------- panel / x-slab loaders for proj ----------------
__device__ __forceinline__ void ld_panel_half(uint32_t (*wp)[136], const uint32_t* base, int koff, int tid)
{
    int m4 = (tid & 31) * 4, kb = tid >> 5;
    #pragma unroll
    for (int it = 0; it < 8; it++) {
        int k2 = koff + kb + it * 8;
        *(uint4*)&wp[k2][m4] = *(const uint4*)(base + (size_t)k2 * 384 + m4);
    }
}
__device__ __forceinline__ void pf_panel_half(uint4 (&r)[8], const uint32_t* base, int tid)
{
    int m4 = (tid & 31) * 4, kb = tid >> 5;
    #pragma unroll
    for (int it = 0; it < 8; it++)
        r[it] = *(const uint4*)(base + (size_t)(kb + it * 8) * 384 + m4);
}
__device__ __forceinline__ void st_panel_half(uint32_t (*wp)[136], uint4 (&r)[8], int tid)
{
    int m4 = (tid & 31) * 4, kb = tid >> 5;
    #pragma unroll
    for (int it = 0; it < 8; it++)
        *(uint4*)&wp[kb + it * 8][m4] = r[it];
}
__device__ __forceinline__ void load_xs(uint32_t (*xs)[136], const float* xg, int tid)
{
    int c = (tid & 31) * 4, kb = tid >> 5;
    #pragma unroll
    for (int it = 0; it < 16; it++) {
        int k2 = kb + it * 8;
        const float* p = xg + (size_t)(2 * k2) * NN + c;
        float4 u = *(const float4*)p;
        float4 v = *(const float4*)(p + NN);
        xs[k2][c + 0] = bf2(u.x, v.x);
        xs[k2][c + 1] = bf2(u.y, v.y);
        xs[k2][c + 2] = bf2(u.z, v.z);
        xs[k2][c + 3] = bf2(u.w, v.w);
    }
}

// ---------------- Kernel 0: pack weights + zero sums + zero Mred ----------------
__global__ __launch_bounds__(256) void pack_kernel(
    const float* __restrict__ tw, const float* __restrict__ tb,
    const float* __restrict__ pw, const float* __restrict__ pb,
    const float* __restrict__ gw, const float* __restrict__ gb,
    const float* __restrict__ Ww)
{
    int i = blockIdx.x * 256 + threadIdx.x;   // 0 .. 49151
    {
        int k2 = i / 384, m = i - k2 * 384;
        const float* w = (m < 128) ? tw : (m < 256) ? pw : gw;
        float2 v = *(const float2*)(w + (size_t)(m & 127) * 256 + 2 * k2);
        d_Wtp[i] = bf2(v.x, v.y);
    }
    if (i < 64 * 256) {
        int d2 = i >> 8, c = i & 255;
        const float* p = Ww + (size_t)c * 128 + 2 * d2;
        d_Wt2p[i] = bf2(p[0], p[1]);
    }
    if (i < 384) d_bias[i] = (i < 128) ? tb[i] : (i < 256) ? pb[i - 128] : gb[i - 256];
    if (i < 512) d_sums[i] = 0.0f;
    // zero d_Mred: 262144 floats = 65536 float4
    const float4 z4 = make_float4(0.f, 0.f, 0.f, 0.f);
    for (int j = i; j < 65536; j += 192 * 256)
        ((float4*)d_Mred)[j] = z4;
}

// ---------------- Kernel 1: fused theta/phi/g projections + atomic M reduce ----------------
// 2 n-slices per block; weight panels register-prefetched under the mma stream.
__global__ __launch_bounds__(256, 1) void proj_fused_kernel(const float* __restrict__ x)
{
    extern __shared__ uint32_t sm32[];
    uint32_t (*xs)[136] = (uint32_t(*)[136])sm32;          // 128 rows
    uint32_t (*wp)[136] = xs + 128;                        // 128 rows
    uint32_t (*ps)[136] = wp + 128;                        // 64 rows
    uint32_t (*gs)[136] = ps + 64;                         // 64 rows
    WARP_IDX
    const int b = blockIdx.y, s = blockIdx.x;
    const float* xbase = x + (size_t)b * CC * NN;

    float accM[4][4][4] = {};
    uint4 pf[8];

    // initial: x slab for half 0 + full theta panel
    load_xs(xs, xbase + 2 * s * 128, tid);
    ld_panel_half(wp, d_Wtp, 0, tid);
    ld_panel_half(wp, d_Wtp, 64, tid);
    __syncthreads();

    #pragma unroll
    for (int half = 0; half < 2; half++) {
        const int n0 = (2 * s + half) * 128;

        // ---- theta GEMM (phi lower half prefetched under it) ----
        pf_panel_half(pf, d_Wtp + 128, tid);
        {
            float acc[4][4][4] = {};
            #pragma unroll
            for (int st = 0; st < 16; st++)
                mma_tile16(wp + st * 8, xs + st * 8, acc, wm, wn, gid, tig);
            uint32_t* T = d_theta + (size_t)b * INTER * (NN / 2) + n0 / 2;
            #pragma unroll
            for (int mt = 0; mt < 4; mt++) {
                int r0 = wm + mt * 16 + gid, r1 = r0 + 8;
                float b0 = d_bias[r0], b1 = d_bias[r1];
                #pragma unroll
                for (int nt = 0; nt < 4; nt++) {
                    int cw = (wn + nt * 8 + 2 * tig) >> 1;
                    T[(size_t)r0 * (NN / 2) + cw] = bf2(acc[mt][nt][0] + b0, acc[mt][nt][1] + b0);
                    T[(size_t)r1 * (NN / 2) + cw] = bf2(acc[mt][nt][2] + b1, acc[mt][nt][3] + b1);
                }
            }
        }
        __syncthreads();
        st_panel_half(wp, pf, tid);
        ld_panel_half(wp, d_Wtp + 128, 64, tid);
        __syncthreads();

        // ---- phi GEMM (g lower half prefetched under it) ----
        pf_panel_half(pf, d_Wtp + 256, tid);
        {
            float acc[4][4][4] = {};
            #pragma unroll
            for (int st = 0; st < 16; st++)
                mma_tile16(wp + st * 8, xs + st * 8, acc, wm, wn, gid, tig);
            #pragma unroll
            for (int mt = 0; mt < 4; mt++) {
                int r0 = wm + mt * 16 + gid, r1 = r0 + 8;
                float b0 = d_bias[128 + r0], b1 = d_bias[128 + r1];
                #pragma unroll
                for (int nt = 0; nt < 4; nt++) {
                    int n2 = (wn + nt * 8 + 2 * tig) >> 1;
                    ps[n2][r0] = bf2(acc[mt][nt][0] + b0, acc[mt][nt][1] + b0);
                    ps[n2][r1] = bf2(acc[mt][nt][2] + b1, acc[mt][nt][3] + b1);
                }
            }
        }
        __syncthreads();
        st_panel_half(wp, pf, tid);
        ld_panel_half(wp, d_Wtp + 256, 64, tid);
        __syncthreads();

        // ---- g GEMM (theta lower for next half prefetched under it) ----
        if (half == 0) pf_panel_half(pf, d_Wtp, tid);
        {
            float acc[4][4][4] = {};
            #pragma unroll
            for (int st = 0; st < 16; st++)
                mma_tile16(wp + st * 8, xs + st * 8, acc, wm, wn, gid, tig);
            #pragma unroll
            for (int mt = 0; mt < 4; mt++) {
                int r0 = wm + mt * 16 + gid, r1 = r0 + 8;
                float b0 = d_bias[256 + r0], b1 = d_bias[256 + r1];
                #pragma unroll
                for (int nt = 0; nt < 4; nt++) {
                    int n2 = (wn + nt * 8 + 2 * tig) >> 1;
                    gs[n2][r0] = bf2(acc[mt][nt][0] + b0, acc[mt][nt][1] + b0);
                    gs[n2][r1] = bf2(acc[mt][nt][2] + b1, acc[mt][nt][3] + b1);
                }
            }
        }
        __syncthreads();
        if (half == 0) {
            // next-half theta panel + x slab: issued here, latency hidden by GEMM_M
            st_panel_half(wp, pf, tid);
            ld_panel_half(wp, d_Wtp, 64, tid);
            load_xs(xs, xbase + (n0 + 128), tid);
        }
        // ---- M partial accumulate ----
        #pragma unroll
        for (int s2 = 0; s2 < 8; s2++)
            mma_tile16(ps + s2 * 8, gs + s2 * 8, accM, wm, wn, gid, tig);
        __syncthreads();
    }
    // atomic split-K reduction straight into d_Mred (mred kernel eliminated)
    red_tile(d_Mred + (size_t)b * INTER * INTER, INTER, accM, wm, wn, gid, tig);
}

// ---------------- Kernel 2: Qt[k][c] = sum_d (Mred[k][d]/N) * Wt2[d][c]  (bf16) ----------------
__global__ __launch_bounds__(256, 2) void q_kernel()
{
    extern __shared__ uint32_t qsm[];
    uint32_t (*As)[136] = (uint32_t(*)[136])qsm;   // 64 rows: [d2][k] pairs along d
    uint32_t (*Bs)[136] = As + 64;                 // 64 rows: [d2][c]
    float acc[4][4][4] = {};
    WARP_IDX
    const int b = blockIdx.y, n0 = blockIdx.x * 128;
    const float* M = d_Mred + (size_t)b * INTER * INTER;
    const float inv = 1.0f / (float)NN;
    // A: transpose + scale + cvt (pairs along d)
    {
        int r = tid >> 1, dq = (tid & 1) * 8;
        #pragma unroll
        for (int st = 0; st < 8; st++) {
            const float* p = M + (size_t)r * INTER + st * 16 + dq;
            float4 v0 = *(const float4*)p, v1 = *(const float4*)(p + 4);
            int q2 = st * 8 + (tid & 1) * 4;
            As[q2 + 0][r] = bf2(v0.x * inv, v0.y * inv);
            As[q2 + 1][r] = bf2(v0.z * inv, v0.w * inv);
            As[q2 + 2][r] = bf2(v1.x * inv, v1.y * inv);
            As[q2 + 3][r] = bf2(v1.z * inv, v1.w * inv);
        }
    }
    // B: straight copy slice of pre-packed W_w^T
    {
        int r = tid >> 2, c0 = (tid & 3) * 4;
        #pragma unroll
        for (int it = 0; it < 8; it++) {
            int c = c0 + it * 16;
            *(uint4*)&Bs[r][c] = *(const uint4*)(d_Wt2p + (size_t)r * 256 + n0 + c);
        }
    }
    __syncthreads();
    #pragma unroll
    for (int st = 0; st < 8; st++)
        mma_tile16(As + st * 8, Bs + st * 8, acc, wm, wn, gid, tig);
    store_tile(d_Qt + (size_t)b * INTER * CC + n0, CC, nullptr, acc, wm, wn, gid, tig);
}

// ---------------- bf16-pair loaders for z ----------------
__device__ __forceinline__ void ld_pair_f32(uint32_t (*S)[136], const float* src, size_t ld, int tid)
{
    int k2 = tid >> 5, c = (tid & 31) * 4;
    const float* p = src + (size_t)(2 * k2) * ld + c;
    float4 u = *(const float4*)p;
    float4 v = *(const float4*)(p + ld);
    S[k2][c + 0] = bf2(u.x, v.x);
    S[k2][c + 1] = bf2(u.y, v.y);
    S[k2][c + 2] = bf2(u.z, v.z);
    S[k2][c + 3] = bf2(u.w, v.w);
}
__device__ __forceinline__ void ld_pair_bf(uint32_t (*S)[136], const uint32_t* src, size_t ldw, int tid)
{
    int k2 = tid >> 5, c2 = (tid & 31) * 2;
    const uint32_t* p = src + (size_t)(2 * k2) * ldw + c2;
    uint32_t w00 = p[0], w01 = p[1];
    uint32_t w10 = p[ldw], w11 = p[ldw + 1];
    S[k2][c2 * 2 + 0] = __byte_perm(w00, w10, 0x5410);
    S[k2][c2 * 2 + 1] = __byte_perm(w00, w10, 0x7632);
    S[k2][c2 * 2 + 2] = __byte_perm(w01, w11, 0x5410);
    S[k2][c2 * 2 + 3] = __byte_perm(w01, w11, 0x7632);
}

// ---------------- Kernel 3: z = Q @ theta + W_b (bf16 out) + BN partial stats ----------------
__global__ __launch_bounds__(256, 2) void z_kernel(const float* __restrict__ W_b)
{
    extern __shared__ uint32_t zsm[];
    uint32_t (*As)[136] = (uint32_t(*)[136])zsm;   // 64 rows: [k2][c]
    uint32_t (*Bs)[136] = As + 64;                 // 64 rows: [k2][n]
    float acc[4][4][4] = {};
    WARP_IDX
    const int b = blockIdx.z, m0 = blockIdx.y * 128, n0 = blockIdx.x * 128;
    const float* A = d_Qt + (size_t)b * INTER * CC + m0;            // [k][c]
    const uint32_t* B = d_theta + (size_t)b * INTER * (NN / 2) + n0 / 2;
    #pragma unroll
    for (int st = 0; st < 8; st++) {
        ld_pair_f32(As + st * 8, A + (size_t)st * 16 * CC, CC, tid);
        ld_pair_bf(Bs + st * 8, B + (size_t)st * 16 * (NN / 2), NN / 2, tid);
    }
    __syncthreads();
    #pragma unroll
    for (int st = 0; st < 8; st++)
        mma_tile16(As + st * 8, Bs + st * 8, acc, wm, wn, gid, tig);

    uint32_t* zb = d_zb + ((size_t)b * CC + m0) * (NN / 2) + n0 / 2;
    #pragma unroll
    for (int mt = 0; mt < 4; mt++) {
        int r0 = wm + mt * 16 + gid, r1 = r0 + 8;
        float b0 = W_b[m0 + r0], b1 = W_b[m0 + r1];
        float s0 = 0.f, q0 = 0.f, s1 = 0.f, q1 = 0.f;
        #pragma unroll
        for (int nt = 0; nt < 4; nt++) {
            int cn = wn + nt * 8 + 2 * tig;
            float v00 = acc[mt][nt][0] + b0, v01 = acc[mt][nt][1] + b0;
            float v10 = acc[mt][nt][2] + b1, v11 = acc[mt][nt][3] + b1;
            zb[(size_t)r0 * (NN / 2) + (cn >> 1)] = bf2(v00, v01);
            zb[(size_t)r1 * (NN / 2) + (cn >> 1)] = bf2(v10, v11);
            s0 += v00 + v01;  q0 += v00 * v00 + v01 * v01;
            s1 += v10 + v11;  q1 += v10 * v10 + v11 * v11;
        }
        s0 += __shfl_xor_sync(~0u, s0, 1); s0 += __shfl_xor_sync(~0u, s0, 2);
        q0 += __shfl_xor_sync(~0u, q0, 1); q0 += __shfl_xor_sync(~0u, q0, 2);
        s1 += __shfl_xor_sync(~0u, s1, 1); s1 += __shfl_xor_sync(~0u, s1, 2);
        q1 += __shfl_xor_sync(~0u, q1, 1); q1 += __shfl_xor_sync(~0u, q1, 2);
        if (tig == 0) {
            atomicAdd(&d_sums[m0 + r0], s0);       atomicAdd(&d_sums[256 + m0 + r0], q0);
            atomicAdd(&d_sums[m0 + r1], s1);       atomicAdd(&d_sums[256 + m0 + r1], q1);
        }
    }
}

// ---------------- Kernel 4: out = z*scale + shift + x (stats finalized inline) ----------------
__global__ __launch_bounds__(256) void bn_apply_kernel(
    const float* __restrict__ x, float* __restrict__ out,
    const float* __restrict__ gamma, const float* __restrict__ beta)
{
    const size_t i = (size_t)blockIdx.x * 256 + threadIdx.x;  // float4 index
    const int c = (int)((i >> 9) & (CC - 1));
    const float inv = 1.0f / (float)(BB * NN);
    float mean = d_sums[c] * inv;
    float var  = d_sums[256 + c] * inv - mean * mean;
    float sc   = gamma[c] * rsqrtf(var + 1e-5f);
    float sh   = beta[c] - mean * sc;
    uint2 zp = ((const uint2*)d_zb)[i];
    float4 xv = ((const float4*)x)[i];
    float z0 = __uint_as_float(zp.x << 16);
    float z1 = __uint_as_float(zp.x & 0xffff0000u);
    float z2 = __uint_as_float(zp.y << 16);
    float z3 = __uint_as_float(zp.y & 0xffff0000u);
    float4 o;
    o.x = z0 * sc + sh + xv.x;
    o.y = z1 * sc + sh + xv.y;
    o.z = z2 * sc + sh + xv.z;
    o.w = z3 * sc + sh + xv.w;
    ((float4*)out)[i] = o;
}

// ---------------- launch ----------------
extern "C" void kernel_launch(void* const* d_in, const int* in_sizes, int n_in,
                              void* d_out, int out_size)
{
    const float* x       = (const float*)d_in[0];
    const float* g_w     = (const float*)d_in[1];
    const float* g_b     = (const float*)d_in[2];
    const float* theta_w = (const float*)d_in[3];
    const float* theta_b = (const float*)d_in[4];
    const float* phi_w   = (const float*)d_in[5];
    const float* phi_b   = (const float*)d_in[6];
    const float* W_w     = (const float*)d_in[7];
    const float* W_b     = (const float*)d_in[8];
    const float* gamma   = (const float*)d_in[9];
    const float* beta    = (const float*)d_in[10];
    float* out = (float*)d_out;

    const int pf_smem = (128 + 128 + 64 + 64) * 136 * 4;   // 208896
    const int q_smem  = (64 + 64) * 136 * 4;               // 69632
    const int z_smem  = (64 + 64) * 136 * 4;               // 69632
    static bool attr_set = false;
    if (!attr_set) {
        cudaFuncSetAttribute(proj_fused_kernel, cudaFuncAttributeMaxDynamicSharedMemorySize, pf_smem);
        cudaFuncSetAttribute(q_kernel, cudaFuncAttributeMaxDynamicSharedMemorySize, q_smem);
        cudaFuncSetAttribute(z_kernel, cudaFuncAttributeMaxDynamicSharedMemorySize, z_smem);
        attr_set = true;
    }

    pack_kernel      <<<192, 256>>>(theta_w, theta_b, phi_w, phi_b, g_w, g_b, W_w);
    proj_fused_kernel<<<dim3(MSPLIT, BB), 256, pf_smem>>>(x);
    q_kernel         <<<dim3(2, BB), 256, q_smem>>>();
    z_kernel         <<<dim3(NN / 128, 2, BB), 256, z_smem>>>(W_b);
    bn_apply_kernel  <<<(size_t)(BB * CC * NN) / 4 / 256, 256>>>(x, out, gamma, beta);
}